// round 7
// baseline (speedup 1.0000x reference)
#include <cuda_runtime.h>
#include <cuda_bf16.h>
#include <math.h>
#include <stdint.h>

#define B_    64
#define FULLN 513
#define E_    768
#define NB    32
#define H_    12
#define HD    64
#define BH    (B_ * H_)       // 768
#define E4    (E_ / 4)        // 192
#define KE    2304            // extended K = 3 * 768

// -------- scratch (device globals; no allocation allowed) --------
__device__ float g_sampled[B_ * NB * E_];
__device__ float g_q[B_ * E_];
__device__ float g_T[BH * E_];
__device__ float g_TK[BH * E_];
__device__ float g_ao[B_ * E_];

// bf16 extended operands.  A-mode segments: (hi, lo, hi); B-mode: (hi, hi, lo)
__device__ __nv_bfloat16 g_ext1[E_ * KE];    // T-ext, then US-ext (A-mode, reused)
__device__ __nv_bfloat16 g_Uext[E_ * KE];    // U-ext (A-mode)
__device__ __nv_bfloat16 g_Wsext[E_ * KE];   // Ws rows       (B-mode)
__device__ __nv_bfloat16 g_Wstext[E_ * KE];  // Ws^T rows     (B-mode)
__device__ __nv_bfloat16 g_Wq[E_ * KE];      // Wq rows (B-mode)
__device__ __nv_bfloat16 g_Wv[E_ * KE];      // Wv rows (B-mode)
__device__ __nv_bfloat16 g_Wo[E_ * KE];      // Wo rows (B-mode)
__device__ __nv_bfloat16 g_bioext[B_ * KE];  // bio (A-mode)
__device__ __nv_bfloat16 g_ctxext[B_ * KE];  // ctx (A-mode)

// ================= mma.sync helpers (baseline PTX, sm_80+) =================
__device__ __forceinline__ uint32_t smem_u32(const void* p) {
    uint32_t a;
    asm("{ .reg .u64 t; cvta.to.shared.u64 t, %1; cvt.u32.u64 %0, t; }" : "=r"(a) : "l"(p));
    return a;
}
__device__ __forceinline__ void ldsm_x4(uint32_t addr, uint32_t& r0, uint32_t& r1,
                                        uint32_t& r2, uint32_t& r3) {
    asm volatile("ldmatrix.sync.aligned.m8n8.x4.shared.b16 {%0,%1,%2,%3}, [%4];"
                 : "=r"(r0), "=r"(r1), "=r"(r2), "=r"(r3) : "r"(addr));
}
__device__ __forceinline__ void mma16816(float* d, const uint32_t* a, const uint32_t* b) {
    asm volatile("mma.sync.aligned.m16n8k16.row.col.f32.bf16.bf16.f32 "
                 "{%0,%1,%2,%3}, {%4,%5,%6,%7}, {%8,%9}, {%0,%1,%2,%3};"
                 : "+f"(d[0]), "+f"(d[1]), "+f"(d[2]), "+f"(d[3])
                 : "r"(a[0]), "r"(a[1]), "r"(a[2]), "r"(a[3]), "r"(b[0]), "r"(b[1]));
}
__device__ __forceinline__ void st_hilo_pair(__nv_bfloat16* base, float x, float y) {
    __nv_bfloat16 hx = __float2bfloat16(x), hy = __float2bfloat16(y);
    __nv_bfloat16 lx = __float2bfloat16(x - __bfloat162float(hx));
    __nv_bfloat16 ly = __float2bfloat16(y - __bfloat162float(hy));
    __nv_bfloat162 hp; hp.x = hx; hp.y = hy;
    __nv_bfloat162 lp; lp.x = lx; lp.y = ly;
    *(__nv_bfloat162*)(base) = hp;
    *(__nv_bfloat162*)(base + E_) = lp;
    *(__nv_bfloat162*)(base + 2 * E_) = hp;
}

// ================= unified HMMA GEMM (no split-K) =================
// C[m, col0 + n] = sum_k Aext[zb][m,k] * Bext[zb][n,k] + bias[col]
#define CH    32
#define ROWB  80
#define TILEB (64 * ROWB)
#define BUFB  (2 * TILEB)

__global__ void __launch_bounds__(256) hmma_kernel(
    const __nv_bfloat16* __restrict__ Aext, long lda, long sAz,
    const __nv_bfloat16* __restrict__ Bext, long sBz,
    const float* __restrict__ bias,
    float* __restrict__ Cout, __nv_bfloat16* __restrict__ extOut,
    int nOffMul, int kLen)
{
    __shared__ __align__(16) char smem[2 * BUFB];
    const int tid = threadIdx.x;
    const int w = tid >> 5, lane = tid & 31;
    const int m0 = blockIdx.y * 64;
    const int n0 = blockIdx.x * 64;
    const int zb = blockIdx.z;
    const int wm = w & 1, wn = w >> 1;

    const uint32_t sbase = smem_u32(smem);

    const int row = tid >> 2, seg = tid & 3;
    const __nv_bfloat16* gA = Aext + zb * sAz + (long)(m0 + row) * lda + seg * 8;
    const __nv_bfloat16* gB = Bext + zb * sBz + (long)(n0 + row) * KE + seg * 8;
    const uint32_t stOff = row * ROWB + seg * 16;

    float acc[2][2][4];
#pragma unroll
    for (int i = 0; i < 2; i++)
#pragma unroll
        for (int j = 0; j < 2; j++)
#pragma unroll
            for (int v = 0; v < 4; v++) acc[i][j][v] = 0.f;

    const int cnum = kLen / CH;
    {
        uint4 a0 = *(const uint4*)gA;
        uint4 b0 = *(const uint4*)gB;
        *(uint4*)(smem + stOff) = a0;
        *(uint4*)(smem + TILEB + stOff) = b0;
    }
    uint4 ra = *(const uint4*)(gA + CH);
    uint4 rb = *(const uint4*)(gB + CH);
    __syncthreads();

    const int qq = lane >> 3, r8 = lane & 7;
    const uint32_t aoff = (uint32_t)((wm * 32 + (qq & 1) * 8 + r8) * ROWB + ((qq >> 1) * 8) * 2);
    const uint32_t boff = (uint32_t)(TILEB + (wn * 16 + (qq >> 1) * 8 + r8) * ROWB + ((qq & 1) * 8) * 2);

    for (int c = 0; c < cnum; c++) {
        const uint32_t base = sbase + (c & 1) * BUFB;
#pragma unroll
        for (int s = 0; s < 2; s++) {
            uint32_t af0[4], af1[4], bf[4];
            ldsm_x4(base + boff + s * 32, bf[0], bf[1], bf[2], bf[3]);
            ldsm_x4(base + aoff + s * 32, af0[0], af0[1], af0[2], af0[3]);
            ldsm_x4(base + aoff + 16 * ROWB + s * 32, af1[0], af1[1], af1[2], af1[3]);
            mma16816(acc[0][0], af0, bf + 0);
            mma16816(acc[0][1], af0, bf + 2);
            mma16816(acc[1][0], af1, bf + 0);
            mma16816(acc[1][1], af1, bf + 2);
        }
        if (c + 1 < cnum) {
            char* d = smem + ((c + 1) & 1) * BUFB;
            *(uint4*)(d + stOff) = ra;
            *(uint4*)(d + TILEB + stOff) = rb;
            if (c + 2 < cnum) {
                ra = *(const uint4*)(gA + (long)(c + 2) * CH);
                rb = *(const uint4*)(gB + (long)(c + 2) * CH);
            }
        }
        __syncthreads();
    }

    const int col0 = n0 + zb * nOffMul;
    const int gr = lane >> 2, gc = (lane & 3) * 2;
#pragma unroll
    for (int mi = 0; mi < 2; mi++) {
#pragma unroll
        for (int ni = 0; ni < 2; ni++) {
            int rr = m0 + wm * 32 + mi * 16 + gr;
            int cc = col0 + wn * 16 + ni * 8 + gc;
            float bx = 0.f, by = 0.f;
            if (bias) { bx = bias[cc]; by = bias[cc + 1]; }
            float x0 = acc[mi][ni][0] + bx, y0 = acc[mi][ni][1] + by;
            float x1 = acc[mi][ni][2] + bx, y1 = acc[mi][ni][3] + by;
            if (Cout) {
                *(float2*)(Cout + (long)rr * E_ + cc) = make_float2(x0, y0);
                *(float2*)(Cout + (long)(rr + 8) * E_ + cc) = make_float2(x1, y1);
            }
            if (extOut) {
                st_hilo_pair(extOut + (long)rr * KE + cc, x0, y0);
                st_hilo_pair(extOut + (long)(rr + 8) * KE + cc, x1, y1);
            }
        }
    }
}

// ================= prep_all: all conversions, one launch =================
__global__ void __launch_bounds__(256) prep_all_kernel(
    const float* __restrict__ Ws, const float* __restrict__ Win,
    const float* __restrict__ Wo, const float* __restrict__ bio,
    __nv_bfloat16* __restrict__ wsext, __nv_bfloat16* __restrict__ wstext,
    __nv_bfloat16* __restrict__ wq, __nv_bfloat16* __restrict__ wv,
    __nv_bfloat16* __restrict__ wox, __nv_bfloat16* __restrict__ bioext)
{
    __shared__ float tile[32][33];
    const int tx = threadIdx.x & 31, ty = threadIdx.x >> 5;
    const int bx = blockIdx.x * 32, by = blockIdx.y * 32;
    const int z = blockIdx.z;

    if (z == 0) {
#pragma unroll
        for (int j = 0; j < 4; j++) {
            float xv = Ws[(long)(by + ty + 8 * j) * E_ + bx + tx];
            tile[ty + 8 * j][tx] = xv;
            __nv_bfloat16 h = __float2bfloat16(xv);
            __nv_bfloat16 l = __float2bfloat16(xv - __bfloat162float(h));
            __nv_bfloat16* o = wsext + (long)(by + ty + 8 * j) * KE + bx + tx;
            o[0] = h; o[E_] = h; o[2 * E_] = l;
        }
        __syncthreads();
#pragma unroll
        for (int j = 0; j < 4; j++) {
            float xv = tile[tx][ty + 8 * j];
            __nv_bfloat16 h = __float2bfloat16(xv);
            __nv_bfloat16 l = __float2bfloat16(xv - __bfloat162float(h));
            __nv_bfloat16* o = wstext + (long)(bx + ty + 8 * j) * KE + by + tx;
            o[0] = h; o[E_] = h; o[2 * E_] = l;
        }
    } else if (z <= 3) {
        const float* s = (z == 1) ? Win : (z == 2) ? (Win + 2 * E_ * E_) : Wo;
        __nv_bfloat16* d = (z == 1) ? wq : (z == 2) ? wv : wox;
#pragma unroll
        for (int j = 0; j < 4; j++) {
            int r = by + ty + 8 * j;
            float xv = s[(long)r * E_ + bx + tx];
            __nv_bfloat16 h = __float2bfloat16(xv);
            __nv_bfloat16 l = __float2bfloat16(xv - __bfloat162float(h));
            __nv_bfloat16* o = d + (long)r * KE + bx + tx;
            o[0] = h; o[E_] = h; o[2 * E_] = l;
        }
    } else {
        if (by >= B_) return;
#pragma unroll
        for (int j = 0; j < 4; j++) {
            int r = by + ty + 8 * j;
            if (r >= B_) continue;
            float xv = bio[(long)r * E_ + bx + tx];
            __nv_bfloat16 h = __float2bfloat16(xv);
            __nv_bfloat16 l = __float2bfloat16(xv - __bfloat162float(h));
            __nv_bfloat16* o = bioext + (long)r * KE + bx + tx;
            o[0] = h; o[E_] = l; o[2 * E_] = h;
        }
    }
}

// ================= trilinear sample =================
__global__ void __launch_bounds__(192) sample_kernel(
    const float* __restrict__ x, const float* __restrict__ base,
    const float* __restrict__ off, float* __restrict__ out)
{
    int bp = blockIdx.x;
    int b = bp >> 5, p = bp & 31;

    float cx = fminf(fmaxf(base[p * 3 + 0] + off[bp * 3 + 0], -1.f), 1.f);
    float cy = fminf(fmaxf(base[p * 3 + 1] + off[bp * 3 + 1], -1.f), 1.f);
    float cz = fminf(fmaxf(base[p * 3 + 2] + off[bp * 3 + 2], -1.f), 1.f);

    float ix = (cx + 1.f) * 3.5f;
    float iy = (cy + 1.f) * 3.5f;
    float iz = (cz + 1.f) * 3.5f;
    float fx = floorf(ix), fy = floorf(iy), fz = floorf(iz);
    float wx = ix - fx, wy = iy - fy, wz = iz - fz;
    int x0 = max(0, min(7, (int)fx));
    int y0 = max(0, min(7, (int)fy));
    int z0 = max(0, min(7, (int)fz));
    int x1 = min(7, x0 + 1), y1 = min(7, y0 + 1), z1 = min(7, z0 + 1);

    int r000 = 1 + ((z0 * 8 + y0) * 8 + x0);
    int r001 = 1 + ((z0 * 8 + y0) * 8 + x1);
    int r010 = 1 + ((z0 * 8 + y1) * 8 + x0);
    int r011 = 1 + ((z0 * 8 + y1) * 8 + x1);
    int r100 = 1 + ((z1 * 8 + y0) * 8 + x0);
    int r101 = 1 + ((z1 * 8 + y0) * 8 + x1);
    int r110 = 1 + ((z1 * 8 + y1) * 8 + x0);
    int r111 = 1 + ((z1 * 8 + y1) * 8 + x1);

    float w000 = (1.f - wz) * (1.f - wy) * (1.f - wx);
    float w001 = (1.f - wz) * (1.f - wy) * wx;
    float w010 = (1.f - wz) * wy * (1.f - wx);
    float w011 = (1.f - wz) * wy * wx;
    float w100 = wz * (1.f - wy) * (1.f - wx);
    float w101 = wz * (1.f - wy) * wx;
    float w110 = wz * wy * (1.f - wx);
    float w111 = wz * wy * wx;

    const float4* X = reinterpret_cast<const float4*>(x) + (long)b * FULLN * E4;
    int t = threadIdx.x;
    float4 s = make_float4(0.f, 0.f, 0.f, 0.f);
#define ACC(R, W) { float4 v = X[(R) * E4 + t]; \
        s.x = fmaf(W, v.x, s.x); s.y = fmaf(W, v.y, s.y); \
        s.z = fmaf(W, v.z, s.z); s.w = fmaf(W, v.w, s.w); }
    ACC(r000, w000) ACC(r001, w001) ACC(r010, w010) ACC(r011, w011)
    ACC(r100, w100) ACC(r101, w101) ACC(r110, w110) ACC(r111, w111)
#undef ACC
    reinterpret_cast<float4*>(out)[(long)bp * E4 + t] = s;
}

// ================= T_h = q_h @ Wk_h (K=64) + ext epilogue ===================
__global__ void __launch_bounds__(256) qk_head_kernel(
    const float* __restrict__ q, const float* __restrict__ Wk,
    float* __restrict__ T, __nv_bfloat16* __restrict__ Text)
{
    __shared__ __align__(16) float As[64][68];
    __shared__ __align__(16) float Bs[64][68];
    const int tid = threadIdx.x;
    const int n0 = blockIdx.x * 64;
    const int h = blockIdx.y;

    const int r = tid >> 2, cbase = (tid & 3) * 16;
#pragma unroll
    for (int j = 0; j < 4; j++) {
        int c4 = cbase + j * 4;
        float4 a = *(const float4*)(q + (long)r * E_ + h * HD + c4);
        As[c4 + 0][r] = a.x; As[c4 + 1][r] = a.y;
        As[c4 + 2][r] = a.z; As[c4 + 3][r] = a.w;
        float4 b = *(const float4*)(Wk + (long)(h * HD + r) * E_ + n0 + c4);
        *(float4*)(&Bs[r][c4]) = b;
    }
    __syncthreads();

    const int ty = tid >> 4, tx = tid & 15;
    float acc[4][4];
#pragma unroll
    for (int i = 0; i < 4; i++)
#pragma unroll
        for (int j = 0; j < 4; j++) acc[i][j] = 0.f;

#pragma unroll 8
    for (int k = 0; k < 64; k++) {
        float4 av = *(const float4*)(&As[k][ty * 4]);
        float4 bv = *(const float4*)(&Bs[k][tx * 4]);
        float a[4] = {av.x, av.y, av.z, av.w};
        float b[4] = {bv.x, bv.y, bv.z, bv.w};
#pragma unroll
        for (int i = 0; i < 4; i++)
#pragma unroll
            for (int j = 0; j < 4; j++)
                acc[i][j] = fmaf(a[i], b[j], acc[i][j]);
    }

#pragma unroll
    for (int i = 0; i < 4; i++) {
        int b = ty * 4 + i;
        long bh = (long)b * H_ + h;
#pragma unroll
        for (int j = 0; j < 4; j += 2) {
            int n = n0 + tx * 4 + j;
            float x0 = acc[i][j], x1 = acc[i][j + 1];
            *(float2*)(T + bh * E_ + n) = make_float2(x0, x1);
            st_hilo_pair(Text + bh * KE + n, x0, x1);
        }
    }
}

// ================= fused scores + softmax + US-ext =================
__global__ void __launch_bounds__(128) scores_us_kernel(
    const float* __restrict__ TK, const float* __restrict__ T,
    const float* __restrict__ q, const float* __restrict__ sampled,
    const float* __restrict__ in_proj_b, const float* __restrict__ bs,
    __nv_bfloat16* __restrict__ ext)
{
    int bh = blockIdx.x;
    int b = bh / H_, h = bh % H_;
    __shared__ float tk[E_];
    __shared__ float sc[NB];
    __shared__ float red[4];
    __shared__ float cbs;
    int tid = threadIdx.x;
    int w = tid >> 5, lane = tid & 31;

    const float* TKrow = TK + (long)bh * E_;
    const float* Trow  = T + (long)bh * E_;
    float part = 0.f;
    for (int f = tid; f < E_; f += 128) {
        float t = TKrow[f];
        tk[f] = t;
        part += Trow[f] * bs[f];
    }
    if (tid < HD)
        part += q[(long)b * E_ + h * HD + tid] * in_proj_b[E_ + h * HD + tid];
#pragma unroll
    for (int o = 16; o; o >>= 1) part += __shfl_xor_sync(0xffffffffu, part, o);
    if (lane == 0) red[w] = part;
    __syncthreads();
    if (tid == 0) cbs = red[0] + red[1] + red[2] + red[3];
    __syncthreads();

    float cb = cbs;
#pragma unroll
    for (int pi = 0; pi < 8; pi++) {
        int p = w * 8 + pi;
        const float* srow = sampled + ((long)b * NB + p) * E_;
        float d = 0.f;
        for (int f = lane; f < E_; f += 32) d = fmaf(tk[f], srow[f], d);
#pragma unroll
        for (int o = 16; o; o >>= 1) d += __shfl_xor_sync(0xffffffffu, d, o);
        if (lane == 0) sc[p] = (d + cb) * 0.125f;
    }
    __syncthreads();
    if (tid < NB) {
        float s = sc[tid];
        float m = s;
#pragma unroll
        for (int o = 16; o; o >>= 1) m = fmaxf(m, __shfl_xor_sync(0xffffffffu, m, o));
        float e = expf(s - m);
        float sum = e;
#pragma unroll
        for (int o = 16; o; o >>= 1) sum += __shfl_xor_sync(0xffffffffu, sum, o);
        sc[tid] = e / sum;
    }
    __syncthreads();

    const float4* S = reinterpret_cast<const float4*>(sampled) + (long)b * NB * E4;
    for (int f = tid; f < E4; f += 128) {
        float4 acc = make_float4(0.f, 0.f, 0.f, 0.f);
#pragma unroll 8
        for (int p = 0; p < NB; p++) {
            float wv = sc[p];
            float4 s = S[p * E4 + f];
            acc.x = fmaf(wv, s.x, acc.x); acc.y = fmaf(wv, s.y, acc.y);
            acc.z = fmaf(wv, s.z, acc.z); acc.w = fmaf(wv, s.w, acc.w);
        }
        __nv_bfloat16* e = ext + (long)bh * KE + 4 * f;
        st_hilo_pair(e, acc.x, acc.y);
        st_hilo_pair(e + 2, acc.z, acc.w);
    }
}

// ================= broadcast out =================
__global__ void __launch_bounds__(192) out_kernel(
    const float* __restrict__ ao, const float* __restrict__ conf,
    float4* __restrict__ out)
{
    int b = blockIdx.y, n = blockIdx.x, t = threadIdx.x;
    float s = conf[b];
    float4 v = reinterpret_cast<const float4*>(ao)[b * E4 + t];
    v.x *= s; v.y *= s; v.z *= s; v.w *= s;
    out[((long)b * FULLN + n) * E4 + t] = v;
}

// ================================================================
extern "C" void kernel_launch(void* const* d_in, const int* in_sizes, int n_in,
                              void* d_out, int out_size)
{
    const float* x    = (const float*)d_in[0];
    const float* bio  = (const float*)d_in[1];
    const float* base = (const float*)d_in[2];
    const float* off  = (const float*)d_in[3];
    const float* conf = (const float*)d_in[4];
    const float* Ws   = (const float*)d_in[5];
    const float* bs   = (const float*)d_in[6];
    const float* Win  = (const float*)d_in[7];
    const float* bin  = (const float*)d_in[8];
    const float* Wo   = (const float*)d_in[9];
    const float* bo   = (const float*)d_in[10];
    float* out = (float*)d_out;

    float *sampled, *q, *T, *TK, *ao;
    cudaGetSymbolAddress((void**)&sampled, g_sampled);
    cudaGetSymbolAddress((void**)&q,  g_q);
    cudaGetSymbolAddress((void**)&T,  g_T);
    cudaGetSymbolAddress((void**)&TK, g_TK);
    cudaGetSymbolAddress((void**)&ao, g_ao);

    __nv_bfloat16 *ext1, *Uext, *Wsext, *Wstext, *Wq, *Wv, *Wox, *bioext, *ctxext;
    cudaGetSymbolAddress((void**)&ext1,   g_ext1);
    cudaGetSymbolAddress((void**)&Uext,   g_Uext);
    cudaGetSymbolAddress((void**)&Wsext,  g_Wsext);
    cudaGetSymbolAddress((void**)&Wstext, g_Wstext);
    cudaGetSymbolAddress((void**)&Wq,     g_Wq);
    cudaGetSymbolAddress((void**)&Wv,     g_Wv);
    cudaGetSymbolAddress((void**)&Wox,    g_Wo);
    cudaGetSymbolAddress((void**)&bioext, g_bioext);
    cudaGetSymbolAddress((void**)&ctxext, g_ctxext);

    // 1) trilinear sample
    sample_kernel<<<B_ * NB, 192>>>(x, base, off, sampled);

    // 2) all conversions, one launch
    prep_all_kernel<<<dim3(24, 24, 5), 256>>>(
        Ws, Win, Wo, bio, Wsext, Wstext, Wq, Wv, Wox, bioext);

    // 3) q = bio @ Wq.T + bq
    hmma_kernel<<<dim3(12, 1, 1), 256>>>(
        bioext, KE, 0, Wq, 0, bin, q, nullptr, 0, KE);

    // 4) T_h = q_h @ Wk_h  -> T fp32 + T ext
    qk_head_kernel<<<dim3(12, H_), 256>>>(q, Win + E_ * E_, T, ext1);

    // 5) TK = T @ Ws
    hmma_kernel<<<dim3(12, 12, 1), 256>>>(
        ext1, KE, 0, Wstext, 0, nullptr, TK, nullptr, 0, KE);

    // 6) scores + softmax + US-ext (fused)
    scores_us_kernel<<<BH, 128>>>(TK, T, q, sampled, bin, bs, ext1);

    // 7) U = US @ Ws.T + bs  -> U ext
    hmma_kernel<<<dim3(12, 12, 1), 256>>>(
        ext1, KE, 0, Wsext, 0, bs, nullptr, Uext, 0, KE);

    // 8) ctx_h = U_h @ Wv_h.T + bv  (per-head: A row stride H_*KE, z offset KE)
    hmma_kernel<<<dim3(1, 1, H_), 256>>>(
        Uext, (long)H_ * KE, KE, Wv, (long)HD * KE,
        bin + 2 * E_, nullptr, ctxext, HD, KE);

    // 9) attn_out = ctx @ Wo.T + bo
    hmma_kernel<<<dim3(12, 1, 1), 256>>>(
        ctxext, KE, 0, Wox, 0, bo, ao, nullptr, 0, KE);

    // 10) broadcast * confidence
    out_kernel<<<dim3(FULLN, B_), 192>>>(ao, conf, (float4*)out);
}

// round 8
// speedup vs baseline: 1.6601x; 1.6601x over previous
#include <cuda_runtime.h>
#include <cuda_bf16.h>
#include <math.h>
#include <stdint.h>

#define B_    64
#define FULLN 513
#define E_    768
#define NB    32
#define H_    12
#define HD    64
#define BH    (B_ * H_)       // 768
#define E4    (E_ / 4)        // 192
#define KE    2304            // extended K = 3 * 768

// -------- scratch (device globals; no allocation allowed) --------
__device__ float g_sampled[B_ * NB * E_];
__device__ float g_q[B_ * E_];
__device__ float g_T[BH * E_];
__device__ float g_TK[BH * E_];
__device__ float g_ao[B_ * E_];
__device__ float g_part[4 * B_ * E_];        // split-K partials (skinny gemms)

// bf16 extended operands.  A-mode segments: (hi, lo, hi); B-mode: (hi, hi, lo)
__device__ __nv_bfloat16 g_ext1[E_ * KE];    // T-ext, then US-ext (A-mode, reused)
__device__ __nv_bfloat16 g_Uext[E_ * KE];    // U-ext (A-mode)
__device__ __nv_bfloat16 g_Wsext[E_ * KE];   // Ws rows   (B-mode)
__device__ __nv_bfloat16 g_Wstext[E_ * KE];  // Ws^T rows (B-mode)
__device__ __nv_bfloat16 g_Wq[E_ * KE];      // Wq rows (B-mode)
__device__ __nv_bfloat16 g_Wv[E_ * KE];      // Wv rows (B-mode)
__device__ __nv_bfloat16 g_Wo[E_ * KE];      // Wo rows (B-mode)
__device__ __nv_bfloat16 g_bioext[B_ * KE];  // bio (A-mode)
__device__ __nv_bfloat16 g_ctxext[B_ * KE];  // ctx (A-mode)

// ================= helpers =================
__device__ __forceinline__ uint32_t smem_u32(const void* p) {
    uint32_t a;
    asm("{ .reg .u64 t; cvta.to.shared.u64 t, %1; cvt.u32.u64 %0, t; }" : "=r"(a) : "l"(p));
    return a;
}
__device__ __forceinline__ void ldsm_x4(uint32_t addr, uint32_t& r0, uint32_t& r1,
                                        uint32_t& r2, uint32_t& r3) {
    asm volatile("ldmatrix.sync.aligned.m8n8.x4.shared.b16 {%0,%1,%2,%3}, [%4];"
                 : "=r"(r0), "=r"(r1), "=r"(r2), "=r"(r3) : "r"(addr));
}
__device__ __forceinline__ void mma16816(float* d, const uint32_t* a, const uint32_t* b) {
    asm volatile("mma.sync.aligned.m16n8k16.row.col.f32.bf16.bf16.f32 "
                 "{%0,%1,%2,%3}, {%4,%5,%6,%7}, {%8,%9}, {%0,%1,%2,%3};"
                 : "+f"(d[0]), "+f"(d[1]), "+f"(d[2]), "+f"(d[3])
                 : "r"(a[0]), "r"(a[1]), "r"(a[2]), "r"(a[3]), "r"(b[0]), "r"(b[1]));
}
__device__ __forceinline__ void st_hilo_pair(__nv_bfloat16* base, float x, float y) {
    __nv_bfloat16 hx = __float2bfloat16(x), hy = __float2bfloat16(y);
    __nv_bfloat16 lx = __float2bfloat16(x - __bfloat162float(hx));
    __nv_bfloat16 ly = __float2bfloat16(y - __bfloat162float(hy));
    __nv_bfloat162 hp; hp.x = hx; hp.y = hy;
    __nv_bfloat162 lp; lp.x = lx; lp.y = ly;
    *(__nv_bfloat162*)(base) = hp;
    *(__nv_bfloat162*)(base + E_) = lp;
    *(__nv_bfloat162*)(base + 2 * E_) = hp;
}
#define CP16(saddr, gptr) \
    asm volatile("cp.async.ca.shared.global [%0], [%1], 16;" \
                 :: "r"(saddr), "l"(gptr))
#define CP_COMMIT() asm volatile("cp.async.commit_group;")
#define CP_WAIT1()  asm volatile("cp.async.wait_group 1;")
#define CP_WAIT0()  asm volatile("cp.async.wait_group 0;")

// ================= HMMA GEMM v2: CH=64, cp.async, 3-buffer pipeline ========
// C[m, col0+n] = sum_{k in split sp} Aext[zb][m,k] * Bext[zb][n,k] (+bias, nSplit==1)
// grid (nTiles, mTiles, nZ*nSplit), 256 threads, CTA tile 64x64, warp 32x16.
#define CH2   64
#define ROW2  144                 // 128B data + 16B pad
#define TILE2 (64 * ROW2)         // 9216
#define OPS2  (2 * TILE2)         // 18432 (A + B tiles for one chunk)
#define SMEM2 (3 * OPS2)          // 55296 dynamic

__global__ void __launch_bounds__(256) hmma_kernel(
    const __nv_bfloat16* __restrict__ Aext, long lda, long sAz,
    const __nv_bfloat16* __restrict__ Bext, long sBz,
    const float* __restrict__ bias,
    float* __restrict__ Cout, __nv_bfloat16* __restrict__ extOut,
    int nOffMul, int nSplit, int kLen, long splitStride)
{
    extern __shared__ __align__(16) char smem[];
    const int tid = threadIdx.x;
    const int w = tid >> 5, lane = tid & 31;
    const int m0 = blockIdx.y * 64;
    const int n0 = blockIdx.x * 64;
    const int zb = blockIdx.z / nSplit;
    const int sp = blockIdx.z - zb * nSplit;
    const int wm = w & 1, wn = w >> 1;
    const uint32_t sbase = smem_u32(smem);

    const int kcl  = kLen / nSplit;   // K elems handled by this CTA
    const int cnum = kcl / CH2;       // chunks (>= 9 in all uses)

    // cp.async task mapping: thread covers rows r and r+32, 16B seg sg
    const int r  = tid >> 3;          // 0..31
    const int sg = tid & 7;           // 0..7
    const __nv_bfloat16* gA = Aext + zb * sAz + (long)(m0 + r) * lda + (long)sp * kcl + sg * 8;
    const __nv_bfloat16* gB = Bext + zb * sBz + (long)(n0 + r) * KE  + (long)sp * kcl + sg * 8;
    const uint32_t stA = (uint32_t)(r * ROW2 + sg * 16);
    const uint32_t stB = TILE2 + stA;
    const long gA32 = 32 * lda;
    const long gB32 = (long)32 * KE;

#define ISSUE(c) do { \
        uint32_t bb = sbase + ((c) % 3) * OPS2; \
        const __nv_bfloat16* pa = gA + (long)(c) * CH2; \
        const __nv_bfloat16* pb = gB + (long)(c) * CH2; \
        CP16(bb + stA,             pa); \
        CP16(bb + stA + 32 * ROW2, pa + gA32); \
        CP16(bb + stB,             pb); \
        CP16(bb + stB + 32 * ROW2, pb + gB32); \
        CP_COMMIT(); \
    } while (0)

    float acc[2][2][4];
#pragma unroll
    for (int i = 0; i < 2; i++)
#pragma unroll
        for (int j = 0; j < 2; j++)
#pragma unroll
            for (int v = 0; v < 4; v++) acc[i][j][v] = 0.f;

    ISSUE(0);
    ISSUE(1);

    const int qq = lane >> 3, r8 = lane & 7;
    const uint32_t aoff = (uint32_t)((wm * 32 + (qq & 1) * 8 + r8) * ROW2 + ((qq >> 1) * 8) * 2);
    const uint32_t boff = (uint32_t)(TILE2 + (wn * 16 + (qq >> 1) * 8 + r8) * ROW2 + ((qq & 1) * 8) * 2);

    for (int c = 0; c < cnum; c++) {
        if (c + 1 < cnum) CP_WAIT1(); else CP_WAIT0();
        __syncthreads();
        if (c + 2 < cnum) ISSUE(c + 2);
        const uint32_t base = sbase + (c % 3) * OPS2;
#pragma unroll
        for (int s = 0; s < 4; s++) {            // four k16 steps per 64-chunk
            uint32_t af0[4], af1[4], bf[4];
            ldsm_x4(base + boff + s * 32, bf[0], bf[1], bf[2], bf[3]);
            ldsm_x4(base + aoff + s * 32, af0[0], af0[1], af0[2], af0[3]);
            ldsm_x4(base + aoff + 16 * ROW2 + s * 32, af1[0], af1[1], af1[2], af1[3]);
            mma16816(acc[0][0], af0, bf + 0);
            mma16816(acc[0][1], af0, bf + 2);
            mma16816(acc[1][0], af1, bf + 0);
            mma16816(acc[1][1], af1, bf + 2);
        }
    }
#undef ISSUE

    // ---- epilogue ----
    float* Cp = Cout ? (Cout + (long)sp * splitStride) : nullptr;
    const int col0 = n0 + zb * nOffMul;
    const int gr = lane >> 2, gc = (lane & 3) * 2;
#pragma unroll
    for (int mi = 0; mi < 2; mi++) {
#pragma unroll
        for (int ni = 0; ni < 2; ni++) {
            int rr = m0 + wm * 32 + mi * 16 + gr;
            int cc = col0 + wn * 16 + ni * 8 + gc;
            float bx = 0.f, by = 0.f;
            if (nSplit == 1 && bias) { bx = bias[cc]; by = bias[cc + 1]; }
            float x0 = acc[mi][ni][0] + bx, y0 = acc[mi][ni][1] + by;
            float x1 = acc[mi][ni][2] + bx, y1 = acc[mi][ni][3] + by;
            if (Cp) {
                *(float2*)(Cp + (long)rr * E_ + cc) = make_float2(x0, y0);
                *(float2*)(Cp + (long)(rr + 8) * E_ + cc) = make_float2(x1, y1);
            }
            if (nSplit == 1 && extOut) {
                st_hilo_pair(extOut + (long)rr * KE + cc, x0, y0);
                st_hilo_pair(extOut + (long)(rr + 8) * KE + cc, x1, y1);
            }
        }
    }
}

// ================= split-K reduce (64 x 768), fp32 and/or ext outputs =======
__global__ void __launch_bounds__(256) reduce2_kernel(
    const float* __restrict__ part, const float* __restrict__ bias,
    float* __restrict__ Cout, __nv_bfloat16* __restrict__ extOut, int nSplit)
{
    const int total4 = B_ * E4;   // 12288
    int i = blockIdx.x * blockDim.x + threadIdx.x;
    if (i >= total4) return;
    const float4* P = reinterpret_cast<const float4*>(part);
    float4 s = P[i];
    for (int sp = 1; sp < nSplit; sp++) {
        float4 v = P[(long)sp * total4 + i];
        s.x += v.x; s.y += v.y; s.z += v.z; s.w += v.w;
    }
    int rr = i / E4;
    int cc = (i - rr * E4) * 4;
    if (bias) {
        float4 b = *(const float4*)(bias + cc);
        s.x += b.x; s.y += b.y; s.z += b.z; s.w += b.w;
    }
    if (Cout) reinterpret_cast<float4*>(Cout)[i] = s;
    if (extOut) {
        __nv_bfloat16* e = extOut + (long)rr * KE + cc;
        st_hilo_pair(e, s.x, s.y);
        st_hilo_pair(e + 2, s.z, s.w);
    }
}

// ================= prep_all: all conversions, one launch =================
__global__ void __launch_bounds__(256) prep_all_kernel(
    const float* __restrict__ Ws, const float* __restrict__ Win,
    const float* __restrict__ Wo, const float* __restrict__ bio,
    __nv_bfloat16* __restrict__ wsext, __nv_bfloat16* __restrict__ wstext,
    __nv_bfloat16* __restrict__ wq, __nv_bfloat16* __restrict__ wv,
    __nv_bfloat16* __restrict__ wox, __nv_bfloat16* __restrict__ bioext)
{
    __shared__ float tile[32][33];
    const int tx = threadIdx.x & 31, ty = threadIdx.x >> 5;
    const int bx = blockIdx.x * 32, by = blockIdx.y * 32;
    const int z = blockIdx.z;

    if (z == 0) {
#pragma unroll
        for (int j = 0; j < 4; j++) {
            float xv = Ws[(long)(by + ty + 8 * j) * E_ + bx + tx];
            tile[ty + 8 * j][tx] = xv;
            __nv_bfloat16 h = __float2bfloat16(xv);
            __nv_bfloat16 l = __float2bfloat16(xv - __bfloat162float(h));
            __nv_bfloat16* o = wsext + (long)(by + ty + 8 * j) * KE + bx + tx;
            o[0] = h; o[E_] = h; o[2 * E_] = l;
        }
        __syncthreads();
#pragma unroll
        for (int j = 0; j < 4; j++) {
            float xv = tile[tx][ty + 8 * j];
            __nv_bfloat16 h = __float2bfloat16(xv);
            __nv_bfloat16 l = __float2bfloat16(xv - __bfloat162float(h));
            __nv_bfloat16* o = wstext + (long)(bx + ty + 8 * j) * KE + by + tx;
            o[0] = h; o[E_] = h; o[2 * E_] = l;
        }
    } else if (z <= 3) {
        const float* s = (z == 1) ? Win : (z == 2) ? (Win + 2 * E_ * E_) : Wo;
        __nv_bfloat16* d = (z == 1) ? wq : (z == 2) ? wv : wox;
#pragma unroll
        for (int j = 0; j < 4; j++) {
            int rr = by + ty + 8 * j;
            float xv = s[(long)rr * E_ + bx + tx];
            __nv_bfloat16 h = __float2bfloat16(xv);
            __nv_bfloat16 l = __float2bfloat16(xv - __bfloat162float(h));
            __nv_bfloat16* o = d + (long)rr * KE + bx + tx;
            o[0] = h; o[E_] = h; o[2 * E_] = l;
        }
    } else {
        if (by >= B_) return;
#pragma unroll
        for (int j = 0; j < 4; j++) {
            int rr = by + ty + 8 * j;
            if (rr >= B_) continue;
            float xv = bio[(long)rr * E_ + bx + tx];
            __nv_bfloat16 h = __float2bfloat16(xv);
            __nv_bfloat16 l = __float2bfloat16(xv - __bfloat162float(h));
            __nv_bfloat16* o = bioext + (long)rr * KE + bx + tx;
            o[0] = h; o[E_] = l; o[2 * E_] = h;
        }
    }
}

// ================= trilinear sample =================
__global__ void __launch_bounds__(192) sample_kernel(
    const float* __restrict__ x, const float* __restrict__ base,
    const float* __restrict__ off, float* __restrict__ out)
{
    int bp = blockIdx.x;
    int b = bp >> 5, p = bp & 31;

    float cx = fminf(fmaxf(base[p * 3 + 0] + off[bp * 3 + 0], -1.f), 1.f);
    float cy = fminf(fmaxf(base[p * 3 + 1] + off[bp * 3 + 1], -1.f), 1.f);
    float cz = fminf(fmaxf(base[p * 3 + 2] + off[bp * 3 + 2], -1.f), 1.f);

    float ix = (cx + 1.f) * 3.5f;
    float iy = (cy + 1.f) * 3.5f;
    float iz = (cz + 1.f) * 3.5f;
    float fx = floorf(ix), fy = floorf(iy), fz = floorf(iz);
    float wx = ix - fx, wy = iy - fy, wz = iz - fz;
    int x0 = max(0, min(7, (int)fx));
    int y0 = max(0, min(7, (int)fy));
    int z0 = max(0, min(7, (int)fz));
    int x1 = min(7, x0 + 1), y1 = min(7, y0 + 1), z1 = min(7, z0 + 1);

    int r000 = 1 + ((z0 * 8 + y0) * 8 + x0);
    int r001 = 1 + ((z0 * 8 + y0) * 8 + x1);
    int r010 = 1 + ((z0 * 8 + y1) * 8 + x0);
    int r011 = 1 + ((z0 * 8 + y1) * 8 + x1);
    int r100 = 1 + ((z1 * 8 + y0) * 8 + x0);
    int r101 = 1 + ((z1 * 8 + y0) * 8 + x1);
    int r110 = 1 + ((z1 * 8 + y1) * 8 + x0);
    int r111 = 1 + ((z1 * 8 + y1) * 8 + x1);

    float w000 = (1.f - wz) * (1.f - wy) * (1.f - wx);
    float w001 = (1.f - wz) * (1.f - wy) * wx;
    float w010 = (1.f - wz) * wy * (1.f - wx);
    float w011 = (1.f - wz) * wy * wx;
    float w100 = wz * (1.f - wy) * (1.f - wx);
    float w101 = wz * (1.f - wy) * wx;
    float w110 = wz * wy * (1.f - wx);
    float w111 = wz * wy * wx;

    const float4* X = reinterpret_cast<const float4*>(x) + (long)b * FULLN * E4;
    int t = threadIdx.x;
    float4 s = make_float4(0.f, 0.f, 0.f, 0.f);
#define ACC(R, W) { float4 v = X[(R) * E4 + t]; \
        s.x = fmaf(W, v.x, s.x); s.y = fmaf(W, v.y, s.y); \
        s.z = fmaf(W, v.z, s.z); s.w = fmaf(W, v.w, s.w); }
    ACC(r000, w000) ACC(r001, w001) ACC(r010, w010) ACC(r011, w011)
    ACC(r100, w100) ACC(r101, w101) ACC(r110, w110) ACC(r111, w111)
#undef ACC
    reinterpret_cast<float4*>(out)[(long)bp * E4 + t] = s;
}

// ================= T_h = q_h @ Wk_h (K=64) + ext epilogue ===================
__global__ void __launch_bounds__(256) qk_head_kernel(
    const float* __restrict__ q, const float* __restrict__ Wk,
    float* __restrict__ T, __nv_bfloat16* __restrict__ Text)
{
    __shared__ __align__(16) float As[64][68];
    __shared__ __align__(16) float Bs[64][68];
    const int tid = threadIdx.x;
    const int n0 = blockIdx.x * 64;
    const int h = blockIdx.y;

    const int r = tid >> 2, cbase = (tid & 3) * 16;
#pragma unroll
    for (int j = 0; j < 4; j++) {
        int c4 = cbase + j * 4;
        float4 a = *(const float4*)(q + (long)r * E_ + h * HD + c4);
        As[c4 + 0][r] = a.x; As[c4 + 1][r] = a.y;
        As[c4 + 2][r] = a.z; As[c4 + 3][r] = a.w;
        float4 b = *(const float4*)(Wk + (long)(h * HD + r) * E_ + n0 + c4);
        *(float4*)(&Bs[r][c4]) = b;
    }
    __syncthreads();

    const int ty = tid >> 4, tx = tid & 15;
    float acc[4][4];
#pragma unroll
    for (int i = 0; i < 4; i++)
#pragma unroll
        for (int j = 0; j < 4; j++) acc[i][j] = 0.f;

#pragma unroll 8
    for (int k = 0; k < 64; k++) {
        float4 av = *(const float4*)(&As[k][ty * 4]);
        float4 bv = *(const float4*)(&Bs[k][tx * 4]);
        float a[4] = {av.x, av.y, av.z, av.w};
        float b[4] = {bv.x, bv.y, bv.z, bv.w};
#pragma unroll
        for (int i = 0; i < 4; i++)
#pragma unroll
            for (int j = 0; j < 4; j++)
                acc[i][j] = fmaf(a[i], b[j], acc[i][j]);
    }

#pragma unroll
    for (int i = 0; i < 4; i++) {
        int b = ty * 4 + i;
        long bh = (long)b * H_ + h;
#pragma unroll
        for (int j = 0; j < 4; j += 2) {
            int n = n0 + tx * 4 + j;
            float x0 = acc[i][j], x1 = acc[i][j + 1];
            *(float2*)(T + bh * E_ + n) = make_float2(x0, x1);
            st_hilo_pair(Text + bh * KE + n, x0, x1);
        }
    }
}

// ================= fused scores + softmax + US-ext =================
__global__ void __launch_bounds__(128) scores_us_kernel(
    const float* __restrict__ TK, const float* __restrict__ T,
    const float* __restrict__ q, const float* __restrict__ sampled,
    const float* __restrict__ in_proj_b, const float* __restrict__ bs,
    __nv_bfloat16* __restrict__ ext)
{
    int bh = blockIdx.x;
    int b = bh / H_, h = bh % H_;
    __shared__ float tk[E_];
    __shared__ float sc[NB];
    __shared__ float red[4];
    __shared__ float cbs;
    int tid = threadIdx.x;
    int w = tid >> 5, lane = tid & 31;

    const float* TKrow = TK + (long)bh * E_;
    const float* Trow  = T + (long)bh * E_;
    float part = 0.f;
    for (int f = tid; f < E_; f += 128) {
        float t = TKrow[f];
        tk[f] = t;
        part += Trow[f] * bs[f];
    }
    if (tid < HD)
        part += q[(long)b * E_ + h * HD + tid] * in_proj_b[E_ + h * HD + tid];
#pragma unroll
    for (int o = 16; o; o >>= 1) part += __shfl_xor_sync(0xffffffffu, part, o);
    if (lane == 0) red[w] = part;
    __syncthreads();
    if (tid == 0) cbs = red[0] + red[1] + red[2] + red[3];
    __syncthreads();

    float cb = cbs;
#pragma unroll
    for (int pi = 0; pi < 8; pi++) {
        int p = w * 8 + pi;
        const float* srow = sampled + ((long)b * NB + p) * E_;
        float d = 0.f;
        for (int f = lane; f < E_; f += 32) d = fmaf(tk[f], srow[f], d);
#pragma unroll
        for (int o = 16; o; o >>= 1) d += __shfl_xor_sync(0xffffffffu, d, o);
        if (lane == 0) sc[p] = (d + cb) * 0.125f;
    }
    __syncthreads();
    if (tid < NB) {
        float s = sc[tid];
        float m = s;
#pragma unroll
        for (int o = 16; o; o >>= 1) m = fmaxf(m, __shfl_xor_sync(0xffffffffu, m, o));
        float e = expf(s - m);
        float sum = e;
#pragma unroll
        for (int o = 16; o; o >>= 1) sum += __shfl_xor_sync(0xffffffffu, sum, o);
        sc[tid] = e / sum;
    }
    __syncthreads();

    const float4* S = reinterpret_cast<const float4*>(sampled) + (long)b * NB * E4;
    for (int f = tid; f < E4; f += 128) {
        float4 acc = make_float4(0.f, 0.f, 0.f, 0.f);
#pragma unroll 8
        for (int p = 0; p < NB; p++) {
            float wv = sc[p];
            float4 s = S[p * E4 + f];
            acc.x = fmaf(wv, s.x, acc.x); acc.y = fmaf(wv, s.y, acc.y);
            acc.z = fmaf(wv, s.z, acc.z); acc.w = fmaf(wv, s.w, acc.w);
        }
        __nv_bfloat16* e = ext + (long)bh * KE + 4 * f;
        st_hilo_pair(e, acc.x, acc.y);
        st_hilo_pair(e + 2, acc.z, acc.w);
    }
}

// ================= broadcast out =================
__global__ void __launch_bounds__(192) out_kernel(
    const float* __restrict__ ao, const float* __restrict__ conf,
    float4* __restrict__ out)
{
    int b = blockIdx.y, n = blockIdx.x, t = threadIdx.x;
    float s = conf[b];
    float4 v = reinterpret_cast<const float4*>(ao)[b * E4 + t];
    v.x *= s; v.y *= s; v.z *= s; v.w *= s;
    out[((long)b * FULLN + n) * E4 + t] = v;
}

// ================================================================
extern "C" void kernel_launch(void* const* d_in, const int* in_sizes, int n_in,
                              void* d_out, int out_size)
{
    const float* x    = (const float*)d_in[0];
    const float* bio  = (const float*)d_in[1];
    const float* base = (const float*)d_in[2];
    const float* off  = (const float*)d_in[3];
    const float* conf = (const float*)d_in[4];
    const float* Ws   = (const float*)d_in[5];
    const float* bs   = (const float*)d_in[6];
    const float* Win  = (const float*)d_in[7];
    const float* bin  = (const float*)d_in[8];
    const float* Wo   = (const float*)d_in[9];
    const float* bo   = (const float*)d_in[10];
    float* out = (float*)d_out;

    float *sampled, *q, *T, *TK, *ao, *part;
    cudaGetSymbolAddress((void**)&sampled, g_sampled);
    cudaGetSymbolAddress((void**)&q,    g_q);
    cudaGetSymbolAddress((void**)&T,    g_T);
    cudaGetSymbolAddress((void**)&TK,   g_TK);
    cudaGetSymbolAddress((void**)&ao,   g_ao);
    cudaGetSymbolAddress((void**)&part, g_part);

    __nv_bfloat16 *ext1, *Uext, *Wsext, *Wstext, *Wq, *Wv, *Wox, *bioext, *ctxext;
    cudaGetSymbolAddress((void**)&ext1,   g_ext1);
    cudaGetSymbolAddress((void**)&Uext,   g_Uext);
    cudaGetSymbolAddress((void**)&Wsext,  g_Wsext);
    cudaGetSymbolAddress((void**)&Wstext, g_Wstext);
    cudaGetSymbolAddress((void**)&Wq,     g_Wq);
    cudaGetSymbolAddress((void**)&Wv,     g_Wv);
    cudaGetSymbolAddress((void**)&Wox,    g_Wo);
    cudaGetSymbolAddress((void**)&bioext, g_bioext);
    cudaGetSymbolAddress((void**)&ctxext, g_ctxext);

    cudaFuncSetAttribute(hmma_kernel,
                         cudaFuncAttributeMaxDynamicSharedMemorySize, SMEM2);

    const long spl = (long)B_ * E_;

    // 1) trilinear sample
    sample_kernel<<<B_ * NB, 192>>>(x, base, off, sampled);

    // 2) all conversions, one launch
    prep_all_kernel<<<dim3(24, 24, 5), 256>>>(
        Ws, Win, Wo, bio, Wsext, Wstext, Wq, Wv, Wox, bioext);

    // 3) q = bio @ Wq.T + bq   (split-K=4)
    hmma_kernel<<<dim3(12, 1, 4), 256, SMEM2>>>(
        bioext, KE, 0, Wq, 0, nullptr, part, nullptr, 0, 4, KE, spl);
    reduce2_kernel<<<48, 256>>>(part, bin, q, nullptr, 4);

    // 4) T_h = q_h @ Wk_h  -> T fp32 + T ext
    qk_head_kernel<<<dim3(12, H_), 256>>>(q, Win + E_ * E_, T, ext1);

    // 5) TK = T @ Ws  (big HMMA)
    hmma_kernel<<<dim3(12, 12, 1), 256, SMEM2>>>(
        ext1, KE, 0, Wstext, 0, nullptr, TK, nullptr, 0, 1, KE, 0);

    // 6) scores + softmax + US-ext (fused)
    scores_us_kernel<<<BH, 128>>>(TK, T, q, sampled, bin, bs, ext1);

    // 7) U = US @ Ws.T + bs  (big HMMA) -> U ext
    hmma_kernel<<<dim3(12, 12, 1), 256, SMEM2>>>(
        ext1, KE, 0, Wsext, 0, bs, nullptr, Uext, 0, 1, KE, 0);

    // 8) ctx_h = U_h @ Wv_h.T + bv  (per-head, split-K=4)
    hmma_kernel<<<dim3(1, 1, H_ * 4), 256, SMEM2>>>(
        Uext, (long)H_ * KE, KE, Wv, (long)HD * KE,
        nullptr, part, nullptr, HD, 4, KE, spl);
    reduce2_kernel<<<48, 256>>>(part, bin + 2 * E_, nullptr, ctxext, 4);

    // 9) attn_out = ctx @ Wo.T + bo  (split-K=4)
    hmma_kernel<<<dim3(12, 1, 4), 256, SMEM2>>>(
        ctxext, KE, 0, Wox, 0, nullptr, part, nullptr, 0, 4, KE, spl);
    reduce2_kernel<<<48, 256>>>(part, bo, ao, nullptr, 4);

    // 10) broadcast * confidence
    out_kernel<<<dim3(FULLN, B_), 192>>>(ao, conf, (float4*)out);
}

// round 9
// speedup vs baseline: 1.7273x; 1.0404x over previous
#include <cuda_runtime.h>
#include <cuda_bf16.h>
#include <math.h>
#include <stdint.h>

#define B_    64
#define FULLN 513
#define E_    768
#define NB    32
#define H_    12
#define HD    64
#define BH    (B_ * H_)       // 768
#define E4    (E_ / 4)        // 192
#define KE    2304            // extended K = 3 * 768

// -------- scratch (device globals; no allocation allowed) --------
__device__ float g_sampled[B_ * NB * E_];
__device__ float g_T[BH * E_];
__device__ float g_TK[BH * E_];
__device__ float g_partq[4 * B_ * E_];       // q split-K partials
__device__ float g_part[4 * B_ * E_];        // ctx / ao split-K partials

// bf16 extended operands.  A-mode segments: (hi, lo, hi); B-mode: (hi, hi, lo)
__device__ __nv_bfloat16 g_ext1[E_ * KE];    // T-ext, then US-ext (A-mode, reused)
__device__ __nv_bfloat16 g_Uext[E_ * KE];    // U-ext (A-mode)
__device__ __nv_bfloat16 g_Wsext[E_ * KE];   // Ws rows   (B-mode)
__device__ __nv_bfloat16 g_Wstext[E_ * KE];  // Ws^T rows (B-mode)
__device__ __nv_bfloat16 g_Wq[E_ * KE];      // Wq rows (B-mode)
__device__ __nv_bfloat16 g_Wv[E_ * KE];      // Wv rows (B-mode)
__device__ __nv_bfloat16 g_Wo[E_ * KE];      // Wo rows (B-mode)
__device__ __nv_bfloat16 g_bioext[B_ * KE];  // bio (A-mode)
__device__ __nv_bfloat16 g_ctxext[B_ * KE];  // ctx (A-mode)

// ================= helpers =================
__device__ __forceinline__ uint32_t smem_u32(const void* p) {
    uint32_t a;
    asm("{ .reg .u64 t; cvta.to.shared.u64 t, %1; cvt.u32.u64 %0, t; }" : "=r"(a) : "l"(p));
    return a;
}
__device__ __forceinline__ void ldsm_x4(uint32_t addr, uint32_t& r0, uint32_t& r1,
                                        uint32_t& r2, uint32_t& r3) {
    asm volatile("ldmatrix.sync.aligned.m8n8.x4.shared.b16 {%0,%1,%2,%3}, [%4];"
                 : "=r"(r0), "=r"(r1), "=r"(r2), "=r"(r3) : "r"(addr));
}
__device__ __forceinline__ void mma16816(float* d, const uint32_t* a, const uint32_t* b) {
    asm volatile("mma.sync.aligned.m16n8k16.row.col.f32.bf16.bf16.f32 "
                 "{%0,%1,%2,%3}, {%4,%5,%6,%7}, {%8,%9}, {%0,%1,%2,%3};"
                 : "+f"(d[0]), "+f"(d[1]), "+f"(d[2]), "+f"(d[3])
                 : "r"(a[0]), "r"(a[1]), "r"(a[2]), "r"(a[3]), "r"(b[0]), "r"(b[1]));
}
__device__ __forceinline__ void st_hilo_pair(__nv_bfloat16* base, float x, float y) {
    __nv_bfloat16 hx = __float2bfloat16(x), hy = __float2bfloat16(y);
    __nv_bfloat16 lx = __float2bfloat16(x - __bfloat162float(hx));
    __nv_bfloat16 ly = __float2bfloat16(y - __bfloat162float(hy));
    __nv_bfloat162 hp; hp.x = hx; hp.y = hy;
    __nv_bfloat162 lp; lp.x = lx; lp.y = ly;
    *(__nv_bfloat162*)(base) = hp;
    *(__nv_bfloat162*)(base + E_) = lp;
    *(__nv_bfloat162*)(base + 2 * E_) = hp;
}
#define CP16(saddr, gptr) \
    asm volatile("cp.async.ca.shared.global [%0], [%1], 16;" \
                 :: "r"(saddr), "l"(gptr))
#define CP_COMMIT() asm volatile("cp.async.commit_group;")
#define CP_WAIT1()  asm volatile("cp.async.wait_group 1;")
#define CP_WAIT0()  asm volatile("cp.async.wait_group 0;")

// ================= HMMA GEMM: CH=64, cp.async, 3-buffer pipeline ===========
#define CH2   64
#define ROW2  144
#define TILE2 (64 * ROW2)
#define OPS2  (2 * TILE2)
#define SMEM2 (3 * OPS2)          // 55296

__global__ void __launch_bounds__(256) hmma_kernel(
    const __nv_bfloat16* __restrict__ Aext, long lda, long sAz,
    const __nv_bfloat16* __restrict__ Bext, long sBz,
    const float* __restrict__ bias,
    float* __restrict__ Cout, __nv_bfloat16* __restrict__ extOut,
    int nOffMul, int nSplit, int kLen, long splitStride)
{
    extern __shared__ __align__(16) char smem[];
    const int tid = threadIdx.x;
    const int w = tid >> 5, lane = tid & 31;
    const int m0 = blockIdx.y * 64;
    const int n0 = blockIdx.x * 64;
    const int zb = blockIdx.z / nSplit;
    const int sp = blockIdx.z - zb * nSplit;
    const int wm = w & 1, wn = w >> 1;
    const uint32_t sbase = smem_u32(smem);

    const int kcl  = kLen / nSplit;
    const int cnum = kcl / CH2;

    const int r  = tid >> 3;
    const int sg = tid & 7;
    const __nv_bfloat16* gA = Aext + zb * sAz + (long)(m0 + r) * lda + (long)sp * kcl + sg * 8;
    const __nv_bfloat16* gB = Bext + zb * sBz + (long)(n0 + r) * KE  + (long)sp * kcl + sg * 8;
    const uint32_t stA = (uint32_t)(r * ROW2 + sg * 16);
    const uint32_t stB = TILE2 + stA;
    const long gA32 = 32 * lda;
    const long gB32 = (long)32 * KE;

#define ISSUE(c) do { \
        uint32_t bb = sbase + ((c) % 3) * OPS2; \
        const __nv_bfloat16* pa = gA + (long)(c) * CH2; \
        const __nv_bfloat16* pb = gB + (long)(c) * CH2; \
        CP16(bb + stA,             pa); \
        CP16(bb + stA + 32 * ROW2, pa + gA32); \
        CP16(bb + stB,             pb); \
        CP16(bb + stB + 32 * ROW2, pb + gB32); \
        CP_COMMIT(); \
    } while (0)

    float acc[2][2][4];
#pragma unroll
    for (int i = 0; i < 2; i++)
#pragma unroll
        for (int j = 0; j < 2; j++)
#pragma unroll
            for (int v = 0; v < 4; v++) acc[i][j][v] = 0.f;

    ISSUE(0);
    ISSUE(1);

    const int qq = lane >> 3, r8 = lane & 7;
    const uint32_t aoff = (uint32_t)((wm * 32 + (qq & 1) * 8 + r8) * ROW2 + ((qq >> 1) * 8) * 2);
    const uint32_t boff = (uint32_t)(TILE2 + (wn * 16 + (qq >> 1) * 8 + r8) * ROW2 + ((qq & 1) * 8) * 2);

    for (int c = 0; c < cnum; c++) {
        if (c + 1 < cnum) CP_WAIT1(); else CP_WAIT0();
        __syncthreads();
        if (c + 2 < cnum) ISSUE(c + 2);
        const uint32_t base = sbase + (c % 3) * OPS2;
#pragma unroll
        for (int s = 0; s < 4; s++) {
            uint32_t af0[4], af1[4], bf[4];
            ldsm_x4(base + boff + s * 32, bf[0], bf[1], bf[2], bf[3]);
            ldsm_x4(base + aoff + s * 32, af0[0], af0[1], af0[2], af0[3]);
            ldsm_x4(base + aoff + 16 * ROW2 + s * 32, af1[0], af1[1], af1[2], af1[3]);
            mma16816(acc[0][0], af0, bf + 0);
            mma16816(acc[0][1], af0, bf + 2);
            mma16816(acc[1][0], af1, bf + 0);
            mma16816(acc[1][1], af1, bf + 2);
        }
    }
#undef ISSUE

    float* Cp = Cout ? (Cout + (long)sp * splitStride) : nullptr;
    const int col0 = n0 + zb * nOffMul;
    const int gr = lane >> 2, gc = (lane & 3) * 2;
#pragma unroll
    for (int mi = 0; mi < 2; mi++) {
#pragma unroll
        for (int ni = 0; ni < 2; ni++) {
            int rr = m0 + wm * 32 + mi * 16 + gr;
            int cc = col0 + wn * 16 + ni * 8 + gc;
            float bx = 0.f, by = 0.f;
            if (nSplit == 1 && bias) { bx = bias[cc]; by = bias[cc + 1]; }
            float x0 = acc[mi][ni][0] + bx, y0 = acc[mi][ni][1] + by;
            float x1 = acc[mi][ni][2] + bx, y1 = acc[mi][ni][3] + by;
            if (Cp) {
                *(float2*)(Cp + (long)rr * E_ + cc) = make_float2(x0, y0);
                *(float2*)(Cp + (long)(rr + 8) * E_ + cc) = make_float2(x1, y1);
            }
            if (nSplit == 1 && extOut) {
                st_hilo_pair(extOut + (long)rr * KE + cc, x0, y0);
                st_hilo_pair(extOut + (long)(rr + 8) * KE + cc, x1, y1);
            }
        }
    }
}

// ================= split-K reduce (ctx only): fp32/ext outputs ==============
__global__ void __launch_bounds__(256) reduce2_kernel(
    const float* __restrict__ part, const float* __restrict__ bias,
    float* __restrict__ Cout, __nv_bfloat16* __restrict__ extOut, int nSplit)
{
    const int total4 = B_ * E4;
    int i = blockIdx.x * blockDim.x + threadIdx.x;
    if (i >= total4) return;
    const float4* P = reinterpret_cast<const float4*>(part);
    float4 s = P[i];
    for (int sp = 1; sp < nSplit; sp++) {
        float4 v = P[(long)sp * total4 + i];
        s.x += v.x; s.y += v.y; s.z += v.z; s.w += v.w;
    }
    int rr = i / E4;
    int cc = (i - rr * E4) * 4;
    if (bias) {
        float4 b = *(const float4*)(bias + cc);
        s.x += b.x; s.y += b.y; s.z += b.z; s.w += b.w;
    }
    if (Cout) reinterpret_cast<float4*>(Cout)[i] = s;
    if (extOut) {
        __nv_bfloat16* e = extOut + (long)rr * KE + cc;
        st_hilo_pair(e, s.x, s.y);
        st_hilo_pair(e + 2, s.z, s.w);
    }
}

// ================= prep_all: all conversions, one launch =================
__global__ void __launch_bounds__(256) prep_all_kernel(
    const float* __restrict__ Ws, const float* __restrict__ Win,
    const float* __restrict__ Wo, const float* __restrict__ bio,
    __nv_bfloat16* __restrict__ wsext, __nv_bfloat16* __restrict__ wstext,
    __nv_bfloat16* __restrict__ wq, __nv_bfloat16* __restrict__ wv,
    __nv_bfloat16* __restrict__ wox, __nv_bfloat16* __restrict__ bioext)
{
    __shared__ float tile[32][33];
    const int tx = threadIdx.x & 31, ty = threadIdx.x >> 5;
    const int bx = blockIdx.x * 32, by = blockIdx.y * 32;
    const int z = blockIdx.z;

    if (z == 0) {
#pragma unroll
        for (int j = 0; j < 4; j++) {
            float xv = Ws[(long)(by + ty + 8 * j) * E_ + bx + tx];
            tile[ty + 8 * j][tx] = xv;
            __nv_bfloat16 h = __float2bfloat16(xv);
            __nv_bfloat16 l = __float2bfloat16(xv - __bfloat162float(h));
            __nv_bfloat16* o = wsext + (long)(by + ty + 8 * j) * KE + bx + tx;
            o[0] = h; o[E_] = h; o[2 * E_] = l;
        }
        __syncthreads();
#pragma unroll
        for (int j = 0; j < 4; j++) {
            float xv = tile[tx][ty + 8 * j];
            __nv_bfloat16 h = __float2bfloat16(xv);
            __nv_bfloat16 l = __float2bfloat16(xv - __bfloat162float(h));
            __nv_bfloat16* o = wstext + (long)(bx + ty + 8 * j) * KE + by + tx;
            o[0] = h; o[E_] = h; o[2 * E_] = l;
        }
    } else if (z <= 3) {
        const float* s = (z == 1) ? Win : (z == 2) ? (Win + 2 * E_ * E_) : Wo;
        __nv_bfloat16* d = (z == 1) ? wq : (z == 2) ? wv : wox;
#pragma unroll
        for (int j = 0; j < 4; j++) {
            int rr = by + ty + 8 * j;
            float xv = s[(long)rr * E_ + bx + tx];
            __nv_bfloat16 h = __float2bfloat16(xv);
            __nv_bfloat16 l = __float2bfloat16(xv - __bfloat162float(h));
            __nv_bfloat16* o = d + (long)rr * KE + bx + tx;
            o[0] = h; o[E_] = h; o[2 * E_] = l;
        }
    } else {
        if (by >= B_) return;
#pragma unroll
        for (int j = 0; j < 4; j++) {
            int rr = by + ty + 8 * j;
            if (rr >= B_) continue;
            float xv = bio[(long)rr * E_ + bx + tx];
            __nv_bfloat16 h = __float2bfloat16(xv);
            __nv_bfloat16 l = __float2bfloat16(xv - __bfloat162float(h));
            __nv_bfloat16* o = bioext + (long)rr * KE + bx + tx;
            o[0] = h; o[E_] = l; o[2 * E_] = h;
        }
    }
}

// ================= trilinear sample =================
__global__ void __launch_bounds__(192) sample_kernel(
    const float* __restrict__ x, const float* __restrict__ base,
    const float* __restrict__ off, float* __restrict__ out)
{
    int bp = blockIdx.x;
    int b = bp >> 5, p = bp & 31;

    float cx = fminf(fmaxf(base[p * 3 + 0] + off[bp * 3 + 0], -1.f), 1.f);
    float cy = fminf(fmaxf(base[p * 3 + 1] + off[bp * 3 + 1], -1.f), 1.f);
    float cz = fminf(fmaxf(base[p * 3 + 2] + off[bp * 3 + 2], -1.f), 1.f);

    float ix = (cx + 1.f) * 3.5f;
    float iy = (cy + 1.f) * 3.5f;
    float iz = (cz + 1.f) * 3.5f;
    float fx = floorf(ix), fy = floorf(iy), fz = floorf(iz);
    float wx = ix - fx, wy = iy - fy, wz = iz - fz;
    int x0 = max(0, min(7, (int)fx));
    int y0 = max(0, min(7, (int)fy));
    int z0 = max(0, min(7, (int)fz));
    int x1 = min(7, x0 + 1), y1 = min(7, y0 + 1), z1 = min(7, z0 + 1);

    int r000 = 1 + ((z0 * 8 + y0) * 8 + x0);
    int r001 = 1 + ((z0 * 8 + y0) * 8 + x1);
    int r010 = 1 + ((z0 * 8 + y1) * 8 + x0);
    int r011 = 1 + ((z0 * 8 + y1) * 8 + x1);
    int r100 = 1 + ((z1 * 8 + y0) * 8 + x0);
    int r101 = 1 + ((z1 * 8 + y0) * 8 + x1);
    int r110 = 1 + ((z1 * 8 + y1) * 8 + x0);
    int r111 = 1 + ((z1 * 8 + y1) * 8 + x1);

    float w000 = (1.f - wz) * (1.f - wy) * (1.f - wx);
    float w001 = (1.f - wz) * (1.f - wy) * wx;
    float w010 = (1.f - wz) * wy * (1.f - wx);
    float w011 = (1.f - wz) * wy * wx;
    float w100 = wz * (1.f - wy) * (1.f - wx);
    float w101 = wz * (1.f - wy) * wx;
    float w110 = wz * wy * (1.f - wx);
    float w111 = wz * wy * wx;

    const float4* X = reinterpret_cast<const float4*>(x) + (long)b * FULLN * E4;
    int t = threadIdx.x;
    float4 s = make_float4(0.f, 0.f, 0.f, 0.f);
#define ACC(R, W) { float4 v = X[(R) * E4 + t]; \
        s.x = fmaf(W, v.x, s.x); s.y = fmaf(W, v.y, s.y); \
        s.z = fmaf(W, v.z, s.z); s.w = fmaf(W, v.w, s.w); }
    ACC(r000, w000) ACC(r001, w001) ACC(r010, w010) ACC(r011, w011)
    ACC(r100, w100) ACC(r101, w101) ACC(r110, w110) ACC(r111, w111)
#undef ACC
    reinterpret_cast<float4*>(out)[(long)bp * E4 + t] = s;
}

// ===== T_h = q_h @ Wk_h (K=64), q from 4-way partials + bq; ext epilogue ====
__global__ void __launch_bounds__(256) qk_head_kernel(
    const float* __restrict__ partq, const float* __restrict__ bin,
    const float* __restrict__ Wk,
    float* __restrict__ T, __nv_bfloat16* __restrict__ Text)
{
    __shared__ __align__(16) float As[64][68];
    __shared__ __align__(16) float Bs[64][68];
    const int tid = threadIdx.x;
    const int n0 = blockIdx.x * 64;
    const int h = blockIdx.y;
    const long spl = (long)B_ * E_;

    const int r = tid >> 2, cbase = (tid & 3) * 16;
#pragma unroll
    for (int j = 0; j < 4; j++) {
        int c4 = cbase + j * 4;
        // q[r, h*HD + c4..+3] = sum_sp partq[...] + bq
        long qo = (long)r * E_ + h * HD + c4;
        float4 a = *(const float4*)(partq + qo);
#pragma unroll
        for (int sp = 1; sp < 4; sp++) {
            float4 v = *(const float4*)(partq + sp * spl + qo);
            a.x += v.x; a.y += v.y; a.z += v.z; a.w += v.w;
        }
        float4 bq = *(const float4*)(bin + h * HD + c4);
        a.x += bq.x; a.y += bq.y; a.z += bq.z; a.w += bq.w;
        As[c4 + 0][r] = a.x; As[c4 + 1][r] = a.y;
        As[c4 + 2][r] = a.z; As[c4 + 3][r] = a.w;
        float4 b = *(const float4*)(Wk + (long)(h * HD + r) * E_ + n0 + c4);
        *(float4*)(&Bs[r][c4]) = b;
    }
    __syncthreads();

    const int ty = tid >> 4, tx = tid & 15;
    float acc[4][4];
#pragma unroll
    for (int i = 0; i < 4; i++)
#pragma unroll
        for (int j = 0; j < 4; j++) acc[i][j] = 0.f;

#pragma unroll 8
    for (int k = 0; k < 64; k++) {
        float4 av = *(const float4*)(&As[k][ty * 4]);
        float4 bv = *(const float4*)(&Bs[k][tx * 4]);
        float a[4] = {av.x, av.y, av.z, av.w};
        float b[4] = {bv.x, bv.y, bv.z, bv.w};
#pragma unroll
        for (int i = 0; i < 4; i++)
#pragma unroll
            for (int j = 0; j < 4; j++)
                acc[i][j] = fmaf(a[i], b[j], acc[i][j]);
    }

#pragma unroll
    for (int i = 0; i < 4; i++) {
        int b = ty * 4 + i;
        long bh = (long)b * H_ + h;
#pragma unroll
        for (int j = 0; j < 4; j += 2) {
            int n = n0 + tx * 4 + j;
            float x0 = acc[i][j], x1 = acc[i][j + 1];
            *(float2*)(T + bh * E_ + n) = make_float2(x0, x1);
            st_hilo_pair(Text + bh * KE + n, x0, x1);
        }
    }
}

// ====== fused scores + softmax + US-ext (q bias term from partials) ========
__global__ void __launch_bounds__(128) scores_us_kernel(
    const float* __restrict__ TK, const float* __restrict__ T,
    const float* __restrict__ partq, const float* __restrict__ sampled,
    const float* __restrict__ in_proj_b, const float* __restrict__ bs,
    __nv_bfloat16* __restrict__ ext)
{
    int bh = blockIdx.x;
    int b = bh / H_, h = bh % H_;
    __shared__ float tk[E_];
    __shared__ float sc[NB];
    __shared__ float red[4];
    __shared__ float cbs;
    int tid = threadIdx.x;
    int w = tid >> 5, lane = tid & 31;
    const long spl = (long)B_ * E_;

    const float* TKrow = TK + (long)bh * E_;
    const float* Trow  = T + (long)bh * E_;
    float part = 0.f;
    for (int f = tid; f < E_; f += 128) {
        float t = TKrow[f];
        tk[f] = t;
        part += Trow[f] * bs[f];
    }
    if (tid < HD) {
        long qo = (long)b * E_ + h * HD + tid;
        float qv = partq[qo] + partq[spl + qo] + partq[2 * spl + qo] + partq[3 * spl + qo]
                 + in_proj_b[h * HD + tid];
        part += qv * in_proj_b[E_ + h * HD + tid];
    }
#pragma unroll
    for (int o = 16; o; o >>= 1) part += __shfl_xor_sync(0xffffffffu, part, o);
    if (lane == 0) red[w] = part;
    __syncthreads();
    if (tid == 0) cbs = red[0] + red[1] + red[2] + red[3];
    __syncthreads();

    float cb = cbs;
#pragma unroll
    for (int pi = 0; pi < 8; pi++) {
        int p = w * 8 + pi;
        const float* srow = sampled + ((long)b * NB + p) * E_;
        float d = 0.f;
        for (int f = lane; f < E_; f += 32) d = fmaf(tk[f], srow[f], d);
#pragma unroll
        for (int o = 16; o; o >>= 1) d += __shfl_xor_sync(0xffffffffu, d, o);
        if (lane == 0) sc[p] = (d + cb) * 0.125f;
    }
    __syncthreads();
    if (tid < NB) {
        float s = sc[tid];
        float m = s;
#pragma unroll
        for (int o = 16; o; o >>= 1) m = fmaxf(m, __shfl_xor_sync(0xffffffffu, m, o));
        float e = expf(s - m);
        float sum = e;
#pragma unroll
        for (int o = 16; o; o >>= 1) sum += __shfl_xor_sync(0xffffffffu, sum, o);
        sc[tid] = e / sum;
    }
    __syncthreads();

    const float4* S = reinterpret_cast<const float4*>(sampled) + (long)b * NB * E4;
    for (int f = tid; f < E4; f += 128) {
        float4 acc = make_float4(0.f, 0.f, 0.f, 0.f);
#pragma unroll 8
        for (int p = 0; p < NB; p++) {
            float wv = sc[p];
            float4 s = S[p * E4 + f];
            acc.x = fmaf(wv, s.x, acc.x); acc.y = fmaf(wv, s.y, acc.y);
            acc.z = fmaf(wv, s.z, acc.z); acc.w = fmaf(wv, s.w, acc.w);
        }
        __nv_bfloat16* e = ext + (long)bh * KE + 4 * f;
        st_hilo_pair(e, acc.x, acc.y);
        st_hilo_pair(e + 2, acc.z, acc.w);
    }
}

// ====== broadcast out: fused ao split-K reduce + bias + confidence =========
// grid (NSPL, B_), 192 threads. Each block reduces its row once, writes a
// slice of the N=513 broadcast.
#define ONS 16
__global__ void __launch_bounds__(192) out_kernel(
    const float* __restrict__ part, const float* __restrict__ bo,
    const float* __restrict__ conf, float4* __restrict__ out)
{
    const int b = blockIdx.y, t = threadIdx.x;
    const long spl = (long)B_ * E_;
    long o = (long)b * E_ + 4 * t;
    float4 s = *(const float4*)(part + o);
#pragma unroll
    for (int sp = 1; sp < 4; sp++) {
        float4 v = *(const float4*)(part + sp * spl + o);
        s.x += v.x; s.y += v.y; s.z += v.z; s.w += v.w;
    }
    float4 bb = *(const float4*)(bo + 4 * t);
    float cf = conf[b];
    s.x = (s.x + bb.x) * cf; s.y = (s.y + bb.y) * cf;
    s.z = (s.z + bb.z) * cf; s.w = (s.w + bb.w) * cf;

    const int nlo = blockIdx.x * 33;
    const int nhi = min(nlo + 33, FULLN);
    float4* dst = out + (long)b * FULLN * E4 + t;
    for (int n = nlo; n < nhi; n++)
        dst[(long)n * E4] = s;
}

// ================================================================
extern "C" void kernel_launch(void* const* d_in, const int* in_sizes, int n_in,
                              void* d_out, int out_size)
{
    const float* x    = (const float*)d_in[0];
    const float* bio  = (const float*)d_in[1];
    const float* base = (const float*)d_in[2];
    const float* off  = (const float*)d_in[3];
    const float* conf = (const float*)d_in[4];
    const float* Ws   = (const float*)d_in[5];
    const float* bs   = (const float*)d_in[6];
    const float* Win  = (const float*)d_in[7];
    const float* bin  = (const float*)d_in[8];
    const float* Wo   = (const float*)d_in[9];
    const float* bo   = (const float*)d_in[10];
    float* out = (float*)d_out;

    float *sampled, *T, *TK, *part, *partq;
    cudaGetSymbolAddress((void**)&sampled, g_sampled);
    cudaGetSymbolAddress((void**)&T,     g_T);
    cudaGetSymbolAddress((void**)&TK,    g_TK);
    cudaGetSymbolAddress((void**)&part,  g_part);
    cudaGetSymbolAddress((void**)&partq, g_partq);

    __nv_bfloat16 *ext1, *Uext, *Wsext, *Wstext, *Wq, *Wv, *Wox, *bioext, *ctxext;
    cudaGetSymbolAddress((void**)&ext1,   g_ext1);
    cudaGetSymbolAddress((void**)&Uext,   g_Uext);
    cudaGetSymbolAddress((void**)&Wsext,  g_Wsext);
    cudaGetSymbolAddress((void**)&Wstext, g_Wstext);
    cudaGetSymbolAddress((void**)&Wq,     g_Wq);
    cudaGetSymbolAddress((void**)&Wv,     g_Wv);
    cudaGetSymbolAddress((void**)&Wox,    g_Wo);
    cudaGetSymbolAddress((void**)&bioext, g_bioext);
    cudaGetSymbolAddress((void**)&ctxext, g_ctxext);

    cudaFuncSetAttribute(hmma_kernel,
                         cudaFuncAttributeMaxDynamicSharedMemorySize, SMEM2);

    const long spl = (long)B_ * E_;

    // 1) trilinear sample
    sample_kernel<<<B_ * NB, 192>>>(x, base, off, sampled);

    // 2) all conversions, one launch
    prep_all_kernel<<<dim3(24, 24, 5), 256>>>(
        Ws, Win, Wo, bio, Wsext, Wstext, Wq, Wv, Wox, bioext);

    // 3) q partials = bio @ Wq.T  (split-K=4; reduce fused into consumers)
    hmma_kernel<<<dim3(12, 1, 4), 256, SMEM2>>>(
        bioext, KE, 0, Wq, 0, nullptr, partq, nullptr, 0, 4, KE, spl);

    // 4) T_h = q_h @ Wk_h  (q reduced inline) -> T fp32 + T ext
    qk_head_kernel<<<dim3(12, H_), 256>>>(partq, bin, Win + E_ * E_, T, ext1);

    // 5) TK = T @ Ws  (big HMMA)
    hmma_kernel<<<dim3(12, 12, 1), 256, SMEM2>>>(
        ext1, KE, 0, Wstext, 0, nullptr, TK, nullptr, 0, 1, KE, 0);

    // 6) scores + softmax + US-ext (fused; q bias term from partials)
    scores_us_kernel<<<BH, 128>>>(TK, T, partq, sampled, bin, bs, ext1);

    // 7) U = US @ Ws.T + bs  (big HMMA) -> U ext
    hmma_kernel<<<dim3(12, 12, 1), 256, SMEM2>>>(
        ext1, KE, 0, Wsext, 0, bs, nullptr, Uext, 0, 1, KE, 0);

    // 8) ctx_h = U_h @ Wv_h.T  (per-head, split-K=4) + reduce -> ctx ext
    hmma_kernel<<<dim3(1, 1, H_ * 4), 256, SMEM2>>>(
        Uext, (long)H_ * KE, KE, Wv, (long)HD * KE,
        nullptr, part, nullptr, HD, 4, KE, spl);
    reduce2_kernel<<<48, 256>>>(part, bin + 2 * E_, nullptr, ctxext, 4);

    // 9) ao partials = ctx @ Wo.T  (split-K=4; reduce fused into out)
    hmma_kernel<<<dim3(12, 1, 4), 256, SMEM2>>>(
        ctxext, KE, 0, Wox, 0, nullptr, part, nullptr, 0, 4, KE, spl);

    // 10) out = (reduce(ao) + bo) * confidence, broadcast over N
    out_kernel<<<dim3(ONS, B_), 192>>>(part, bo, conf, (float4*)out);
}